// round 6
// baseline (speedup 1.0000x reference)
#include <cuda_runtime.h>
#include <cuda_bf16.h>

#define ND   16    // domains
#define NE   64    // embedding dim
#define NK   32    // bottleneck dim
#define CAP  8192  // per-domain token-list capacity (expected ~3277)

// ---- device scratch (allocation-free) ----
__device__ float g_Wt1[ND * NK * NE];   // [d][k][e]
__device__ float g_Wt2[ND * NE * NK];   // [d][e][k]
__device__ int   g_cnt[ND];
__device__ int   g_list[ND * CAP];

// ------------------------------------------------------------------
// 1) zero counters + transpose weights
// ------------------------------------------------------------------
__global__ void prep_kernel(const float* __restrict__ W1,
                            const float* __restrict__ W2) {
    int i = blockIdx.x * blockDim.x + threadIdx.x;
    if (i < ND) g_cnt[i] = 0;
    const int total = ND * NE * NK;  // 32768
    if (i >= total) return;
    int d = i >> 11;
    int r = i & 2047;
    int e = r >> 5, k = r & 31;
    g_Wt1[(d << 11) + (k << 6) + e] = W1[i];
    int k2 = r >> 6, e2 = r & 63;
    g_Wt2[(d << 11) + (e2 << 5) + k2] = W2[i];
}

// ------------------------------------------------------------------
// 2) build compacted per-domain token lists (block-aggregated atomics)
// ------------------------------------------------------------------
__global__ __launch_bounds__(256)
void build_lists(const int* __restrict__ x,
                 const unsigned char* __restrict__ membership,
                 int T) {
    __shared__ int scnt[ND];
    __shared__ int sbase[ND];
    const int t = blockIdx.x * 256 + threadIdx.x;
    if (threadIdx.x < ND) scnt[threadIdx.x] = 0;
    __syncthreads();

    unsigned act = 0;
    int mypos[ND];
    if (t < T) {
        const int tok = x[t];
        const unsigned char* __restrict__ mrow = membership + (long)tok * ND;
        #pragma unroll
        for (int d = 0; d < ND; ++d) {
            if (mrow[d]) {
                act |= (1u << d);
                mypos[d] = atomicAdd(&scnt[d], 1);
            }
        }
    }
    __syncthreads();
    if (threadIdx.x < ND)
        sbase[threadIdx.x] = atomicAdd(&g_cnt[threadIdx.x], scnt[threadIdx.x]);
    __syncthreads();
    if (t < T) {
        #pragma unroll
        for (int d = 0; d < ND; ++d) {
            if (act & (1u << d)) {
                int pos = sbase[d] + mypos[d];
                if (pos < CAP) g_list[d * CAP + pos] = t;
            }
        }
    }
}

// ------------------------------------------------------------------
// 3) coalesced base-embedding copy: out[t][:] = table[x[t]][:]
// ------------------------------------------------------------------
__global__ __launch_bounds__(256)
void base_copy(const int* __restrict__ x,
               const float* __restrict__ table,
               float* __restrict__ out,
               int T) {
    const int n4 = T * (NE / 4);
    int i = blockIdx.x * 256 + threadIdx.x;
    if (i >= n4) return;
    const int t = i >> 4;
    const int c = i & 15;
    const int tok = __ldg(x + t);
    const float4 v = __ldg(reinterpret_cast<const float4*>(table) + tok * 16 + c);
    reinterpret_cast<float4*>(out)[i] = v;
}

// ------------------------------------------------------------------
// 4) per-domain MLP: register-resident weights, depth-2 software
//    pipeline, 2-token-interleaved compute.
// ------------------------------------------------------------------
#define BLK_PER_DOM 24
#define MLP_WARPS   4

__global__ __launch_bounds__(MLP_WARPS * 32)
void domain_mlp(const int* __restrict__ x,
                const float* __restrict__ table,
                float* __restrict__ out) {
    __shared__ float hsA[MLP_WARPS][NE];
    __shared__ float hsB[MLP_WARPS][NE];
    __shared__ float usA[MLP_WARPS][NK];
    __shared__ float usB[MLP_WARPS][NK];

    const int w    = threadIdx.x >> 5;
    const int lane = threadIdx.x & 31;
    const int d     = blockIdx.x & 15;
    const int chunk = blockIdx.x >> 4;
    const int ws    = BLK_PER_DOM * MLP_WARPS;   // warps per domain

    int cnt = g_cnt[d];
    if (cnt > CAP) cnt = CAP;

    int iA = chunk * MLP_WARPS + w;
    if (iA >= cnt) return;

    // ---- register-resident domain weights ----
    float4 w1r[16];
    {
        const float4* __restrict__ p =
            reinterpret_cast<const float4*>(g_Wt1 + (d << 11) + (lane << 6));
        #pragma unroll
        for (int i = 0; i < 16; ++i) w1r[i] = p[i];
    }
    float4 w2a[8], w2b[8];
    {
        const float4* __restrict__ pa =
            reinterpret_cast<const float4*>(g_Wt2 + (d << 11) + (lane << 5));
        const float4* __restrict__ pb =
            reinterpret_cast<const float4*>(g_Wt2 + (d << 11) + ((lane + 32) << 5));
        #pragma unroll
        for (int i = 0; i < 8; ++i) { w2a[i] = pa[i]; w2b[i] = pb[i]; }
    }

    const int* __restrict__ list = g_list + d * CAP;

    // ---- prefetch first pair (A = iA, B = iA + ws) ----
    int iB = iA + ws;
    bool vB = (iB < cnt);
    int tA = __ldg(list + iA);
    int tB = vB ? __ldg(list + iB) : tA;
    float2 hA = reinterpret_cast<const float2*>(table + (long)__ldg(x + tA) * NE)[lane];
    float2 hB = reinterpret_cast<const float2*>(table + (long)__ldg(x + tB) * NE)[lane];

    while (true) {
        __syncwarp();   // prior iteration's smem reads complete
        reinterpret_cast<float2*>(hsA[w])[lane] = hA;
        reinterpret_cast<float2*>(hsB[w])[lane] = hB;
        __syncwarp();

        const int  curA = tA, curB = tB;
        const bool curVB = vB;

        // ---- prefetch next pair (overlaps all compute below) ----
        const int nA = iA + 2 * ws, nB = iB + 2 * ws;
        const bool hasNext = (nA < cnt);
        if (hasNext) {
            vB = (nB < cnt);
            tA = __ldg(list + nA);
            tB = vB ? __ldg(list + nB) : tA;
            hA = reinterpret_cast<const float2*>(table + (long)__ldg(x + tA) * NE)[lane];
            hB = reinterpret_cast<const float2*>(table + (long)__ldg(x + tB) * NE)[lane];
        }
        iA = nA; iB = nB;

        // ---- stage 1 (both tokens interleaved): u[k] = gelu(h · W1[:,k]) ----
        const float4* __restrict__ hvA = reinterpret_cast<const float4*>(hsA[w]);
        const float4* __restrict__ hvB = reinterpret_cast<const float4*>(hsB[w]);
        float aA0 = 0.f, aA1 = 0.f, aA2 = 0.f, aA3 = 0.f;
        float aB0 = 0.f, aB1 = 0.f, aB2 = 0.f, aB3 = 0.f;
        #pragma unroll
        for (int i = 0; i < 16; i += 4) {
            float4 q0 = w1r[i], q1 = w1r[i+1], q2 = w1r[i+2], q3 = w1r[i+3];
            float4 bA0 = hvA[i], bA1 = hvA[i+1], bA2 = hvA[i+2], bA3 = hvA[i+3];
            float4 bB0 = hvB[i], bB1 = hvB[i+1], bB2 = hvB[i+2], bB3 = hvB[i+3];
            aA0 = fmaf(q0.x, bA0.x, aA0); aB0 = fmaf(q0.x, bB0.x, aB0);
            aA0 = fmaf(q0.y, bA0.y, aA0); aB0 = fmaf(q0.y, bB0.y, aB0);
            aA0 = fmaf(q0.z, bA0.z, aA0); aB0 = fmaf(q0.z, bB0.z, aB0);
            aA0 = fmaf(q0.w, bA0.w, aA0); aB0 = fmaf(q0.w, bB0.w, aB0);
            aA1 = fmaf(q1.x, bA1.x, aA1); aB1 = fmaf(q1.x, bB1.x, aB1);
            aA1 = fmaf(q1.y, bA1.y, aA1); aB1 = fmaf(q1.y, bB1.y, aB1);
            aA1 = fmaf(q1.z, bA1.z, aA1); aB1 = fmaf(q1.z, bB1.z, aB1);
            aA1 = fmaf(q1.w, bA1.w, aA1); aB1 = fmaf(q1.w, bB1.w, aB1);
            aA2 = fmaf(q2.x, bA2.x, aA2); aB2 = fmaf(q2.x, bB2.x, aB2);
            aA2 = fmaf(q2.y, bA2.y, aA2); aB2 = fmaf(q2.y, bB2.y, aB2);
            aA2 = fmaf(q2.z, bA2.z, aA2); aB2 = fmaf(q2.z, bB2.z, aB2);
            aA2 = fmaf(q2.w, bA2.w, aA2); aB2 = fmaf(q2.w, bB2.w, aB2);
            aA3 = fmaf(q3.x, bA3.x, aA3); aB3 = fmaf(q3.x, bB3.x, aB3);
            aA3 = fmaf(q3.y, bA3.y, aA3); aB3 = fmaf(q3.y, bB3.y, aB3);
            aA3 = fmaf(q3.z, bA3.z, aA3); aB3 = fmaf(q3.z, bB3.z, aB3);
            aA3 = fmaf(q3.w, bA3.w, aA3); aB3 = fmaf(q3.w, bB3.w, aB3);
        }
        const float accA = (aA0 + aA1) + (aA2 + aA3);
        const float accB = (aB0 + aB1) + (aB2 + aB3);
        const float uA = 0.5f * accA * (1.f + erff(accA * 0.70710678118654752f));
        const float uB = 0.5f * accB * (1.f + erff(accB * 0.70710678118654752f));
        usA[w][lane] = uA;
        usB[w][lane] = uB;
        __syncwarp();

        // ---- stage 2 (both tokens interleaved): corr[e] = u · W2[:,e] ----
        const float4* __restrict__ uvA = reinterpret_cast<const float4*>(usA[w]);
        const float4* __restrict__ uvB = reinterpret_cast<const float4*>(usB[w]);
        float cA0 = 0.f, cA1 = 0.f, cB0 = 0.f, cB1 = 0.f;
        #pragma unroll
        for (int i = 0; i < 8; ++i) {
            float4 qa = w2a[i], qb = w2b[i];
            float4 uuA = uvA[i], uuB = uvB[i];
            cA0 = fmaf(qa.x, uuA.x, cA0); cB0 = fmaf(qa.x, uuB.x, cB0);
            cA1 = fmaf(qb.x, uuA.x, cA1); cB1 = fmaf(qb.x, uuB.x, cB1);
            cA0 = fmaf(qa.y, uuA.y, cA0); cB0 = fmaf(qa.y, uuB.y, cB0);
            cA1 = fmaf(qb.y, uuA.y, cA1); cB1 = fmaf(qb.y, uuB.y, cB1);
            cA0 = fmaf(qa.z, uuA.z, cA0); cB0 = fmaf(qa.z, uuB.z, cB0);
            cA1 = fmaf(qb.z, uuA.z, cA1); cB1 = fmaf(qb.z, uuB.z, cB1);
            cA0 = fmaf(qa.w, uuA.w, cA0); cB0 = fmaf(qa.w, uuB.w, cB0);
            cA1 = fmaf(qb.w, uuA.w, cA1); cB1 = fmaf(qb.w, uuB.w, cB1);
        }

        atomicAdd(out + (long)curA * NE + lane,      0.1f * cA0);
        atomicAdd(out + (long)curA * NE + lane + 32, 0.1f * cA1);
        if (curVB) {
            atomicAdd(out + (long)curB * NE + lane,      0.1f * cB0);
            atomicAdd(out + (long)curB * NE + lane + 32, 0.1f * cB1);
        }

        if (!hasNext) break;
    }
}

extern "C" void kernel_launch(void* const* d_in, const int* in_sizes, int n_in,
                              void* d_out, int out_size) {
    const int*           x     = (const int*)d_in[0];
    const float*         table = (const float*)d_in[1];
    const float*         W1    = (const float*)d_in[2];
    const float*         W2    = (const float*)d_in[3];
    const unsigned char* mem   = (const unsigned char*)d_in[4];
    float* out = (float*)d_out;

    const int T = in_sizes[0];

    prep_kernel<<<(ND * NE * NK + 255) / 256, 256>>>(W1, W2);
    build_lists<<<(T + 255) / 256, 256>>>(x, mem, T);
    base_copy<<<(T * (NE / 4) + 255) / 256, 256>>>(x, table, out, T);
    domain_mlp<<<ND * BLK_PER_DOM, MLP_WARPS * 32>>>(x, table, out);
}

// round 7
// speedup vs baseline: 1.1386x; 1.1386x over previous
#include <cuda_runtime.h>
#include <cuda_bf16.h>

#define ND   16    // domains
#define NE   64    // embedding dim
#define NK   32    // bottleneck dim
#define W2S  36    // padded W2 row stride (floats): conflict-free LDS.128
#define CAP  8192  // per-domain token-list capacity (expected ~3277)

// ---- device scratch (allocation-free; __device__ globals are zero-init) ----
__device__ float g_Wt1[ND * NK * NE];      // [d][k][e]
__device__ float g_Wt2p[ND * NE * W2S];    // [d][e][k], k-rows padded to 36
__device__ int   g_cnt[ND];
__device__ int   g_list[ND * CAP];

typedef unsigned long long ull;

// packed fp32x2 FMA (sm_100+/sm_103a; FFMA2 only reachable via PTX)
__device__ __forceinline__ ull ffma2(ull a, ull b, ull c) {
    ull d;
    asm("fma.rn.f32x2 %0, %1, %2, %3;" : "=l"(d) : "l"(a), "l"(b), "l"(c));
    return d;
}
__device__ __forceinline__ float2 unpk(ull v) {
    unsigned lo, hi;
    asm("mov.b64 {%0, %1}, %2;" : "=r"(lo), "=r"(hi) : "l"(v));
    return make_float2(__uint_as_float(lo), __uint_as_float(hi));
}

// ------------------------------------------------------------------
// 1) zero counters + transpose weights
// ------------------------------------------------------------------
__global__ void prep_kernel(const float* __restrict__ W1,
                            const float* __restrict__ W2) {
    int i = blockIdx.x * blockDim.x + threadIdx.x;
    if (i < ND) g_cnt[i] = 0;
    const int total = ND * NE * NK;  // 32768
    if (i >= total) return;
    int d = i >> 11;
    int r = i & 2047;
    // W1 native [d][e][k] -> g_Wt1[d][k][e]
    int e = r >> 5, k = r & 31;
    g_Wt1[(d << 11) + (k << 6) + e] = W1[i];
    // W2 native [d][k][e] -> g_Wt2p[d][e][k] with padded row stride 36
    int k2 = r >> 6, e2 = r & 63;
    g_Wt2p[(d * NE + e2) * W2S + k2] = W2[i];
}

// ------------------------------------------------------------------
// 2) fused: build per-domain token lists + coalesced base copy
// ------------------------------------------------------------------
__global__ __launch_bounds__(256)
void build_copy(const int* __restrict__ x,
                const unsigned char* __restrict__ membership,
                const float* __restrict__ table,
                float* __restrict__ out,
                int T) {
    __shared__ int scnt[ND];
    __shared__ int sbase[ND];
    __shared__ int stok[256];

    const int t = blockIdx.x * 256 + threadIdx.x;
    if (threadIdx.x < ND) scnt[threadIdx.x] = 0;
    __syncthreads();

    unsigned act = 0;
    int mypos[ND];
    if (t < T) {
        const int tok = x[t];
        stok[threadIdx.x] = tok;
        const unsigned char* __restrict__ mrow = membership + (long)tok * ND;
        #pragma unroll
        for (int d = 0; d < ND; ++d) {
            if (mrow[d]) {
                act |= (1u << d);
                mypos[d] = atomicAdd(&scnt[d], 1);
            }
        }
    }
    __syncthreads();
    if (threadIdx.x < ND)
        sbase[threadIdx.x] = atomicAdd(&g_cnt[threadIdx.x], scnt[threadIdx.x]);
    __syncthreads();
    if (t < T) {
        #pragma unroll
        for (int d = 0; d < ND; ++d) {
            if (act & (1u << d)) {
                int pos = sbase[d] + mypos[d];
                if (pos < CAP) g_list[d * CAP + pos] = t;
            }
        }
    }

    // coalesced base-embedding copy for this block's 256 tokens
    const float4* __restrict__ table4 = reinterpret_cast<const float4*>(table);
    float4* __restrict__ out4 = reinterpret_cast<float4*>(out);
    const long blk_base = (long)blockIdx.x * 256;
    #pragma unroll
    for (int j = threadIdx.x; j < 256 * 16; j += 256) {
        const int tl = j >> 4;        // local token
        const int c  = j & 15;        // float4 column
        const long gt = blk_base + tl;
        if (gt < T)
            out4[gt * 16 + c] = __ldg(table4 + (long)stok[tl] * 16 + c);
    }
}

// ------------------------------------------------------------------
// 3) per-domain MLP: W1 register-resident (packed), W2 in smem,
//    packed f32x2 math, depth-2 prefetch, 2-token interleave.
// ------------------------------------------------------------------
#define BLK_PER_DOM 36
#define MLP_WARPS   4

__global__ __launch_bounds__(MLP_WARPS * 32, 4)
void domain_mlp(const int* __restrict__ x,
                const float* __restrict__ table,
                float* __restrict__ out) {
    __shared__ float hsA[MLP_WARPS][NE];
    __shared__ float hsB[MLP_WARPS][NE];
    __shared__ float usA[MLP_WARPS][NK];
    __shared__ float usB[MLP_WARPS][NK];
    __shared__ float sw2[NE * W2S];     // this domain's W2, padded rows

    const int w    = threadIdx.x >> 5;
    const int lane = threadIdx.x & 31;
    const int d     = blockIdx.x & 15;
    const int chunk = blockIdx.x >> 4;
    const int ws    = BLK_PER_DOM * MLP_WARPS;   // warps per domain

    // cooperative W2 tile load (all threads; before any early exit)
    for (int i = threadIdx.x; i < NE * W2S; i += MLP_WARPS * 32)
        sw2[i] = g_Wt2p[d * NE * W2S + i];
    __syncthreads();

    int cnt = g_cnt[d];
    if (cnt > CAP) cnt = CAP;
    int iA = chunk * MLP_WARPS + w;
    if (iA >= cnt) return;

    // ---- W1 row (lane = k) as 32 packed f32x2 regs ----
    ull w1p[32];
    {
        const ulonglong2* __restrict__ p =
            reinterpret_cast<const ulonglong2*>(g_Wt1 + (d << 11) + (lane << 6));
        #pragma unroll
        for (int i = 0; i < 16; ++i) {
            ulonglong2 q = p[i];
            w1p[2 * i]     = q.x;
            w1p[2 * i + 1] = q.y;
        }
    }

    const int* __restrict__ list = g_list + d * CAP;

    // ---- prefetch first pair ----
    int iB = iA + ws;
    bool vB = (iB < cnt);
    int tA = __ldg(list + iA);
    int tB = vB ? __ldg(list + iB) : tA;
    float2 hA = reinterpret_cast<const float2*>(table + (long)__ldg(x + tA) * NE)[lane];
    float2 hB = reinterpret_cast<const float2*>(table + (long)__ldg(x + tB) * NE)[lane];

    const ulonglong2* __restrict__ hpA = reinterpret_cast<const ulonglong2*>(hsA[w]);
    const ulonglong2* __restrict__ hpB = reinterpret_cast<const ulonglong2*>(hsB[w]);
    const ulonglong2* __restrict__ upA = reinterpret_cast<const ulonglong2*>(usA[w]);
    const ulonglong2* __restrict__ upB = reinterpret_cast<const ulonglong2*>(usB[w]);
    const ulonglong2* __restrict__ w2r0 =
        reinterpret_cast<const ulonglong2*>(sw2 + lane * W2S);
    const ulonglong2* __restrict__ w2r1 =
        reinterpret_cast<const ulonglong2*>(sw2 + (lane + 32) * W2S);

    while (true) {
        __syncwarp();
        reinterpret_cast<float2*>(hsA[w])[lane] = hA;
        reinterpret_cast<float2*>(hsB[w])[lane] = hB;
        __syncwarp();

        const int  curA = tA, curB = tB;
        const bool curVB = vB;

        // ---- prefetch next pair (overlaps compute) ----
        const int nA = iA + 2 * ws, nB = iB + 2 * ws;
        const bool hasNext = (nA < cnt);
        if (hasNext) {
            vB = (nB < cnt);
            tA = __ldg(list + nA);
            tB = vB ? __ldg(list + nB) : tA;
            hA = reinterpret_cast<const float2*>(table + (long)__ldg(x + tA) * NE)[lane];
            hB = reinterpret_cast<const float2*>(table + (long)__ldg(x + tB) * NE)[lane];
        }
        iA = nA; iB = nB;

        // ---- stage 1 (packed along e): u[k] = gelu(h · W1[:,k]) ----
        ull a0 = 0, a1 = 0, a2 = 0, a3 = 0;   // token A, 2 chains each... A:(a0,a1) B:(a2,a3)
        ull b0 = 0, b1 = 0;
        #pragma unroll
        for (int i = 0; i < 16; ++i) {
            ulonglong2 qA = hpA[i];
            ulonglong2 qB = hpB[i];
            ull w0 = w1p[2 * i], w1_ = w1p[2 * i + 1];
            a0 = ffma2(w0,  qA.x, a0);
            a1 = ffma2(w1_, qA.y, a1);
            a2 = ffma2(w0,  qB.x, a2);
            a3 = ffma2(w1_, qB.y, a3);
            (void)b0; (void)b1;
        }
        float2 fA0 = unpk(a0), fA1 = unpk(a1);
        float2 fB0 = unpk(a2), fB1 = unpk(a3);
        const float accA = (fA0.x + fA0.y) + (fA1.x + fA1.y);
        const float accB = (fB0.x + fB0.y) + (fB1.x + fB1.y);
        const float uA = 0.5f * accA * (1.f + erff(accA * 0.70710678118654752f));
        const float uB = 0.5f * accB * (1.f + erff(accB * 0.70710678118654752f));
        usA[w][lane] = uA;
        usB[w][lane] = uB;
        __syncwarp();

        // ---- stage 2 (packed along k): corr[e] = u · W2[e][:] ----
        ull cA0 = 0, cA1 = 0, cB0 = 0, cB1 = 0;
        #pragma unroll
        for (int i = 0; i < 8; ++i) {
            ulonglong2 ua = upA[i];
            ulonglong2 ub = upB[i];
            ulonglong2 wa = w2r0[i];
            ulonglong2 wb = w2r1[i];
            cA0 = ffma2(wa.x, ua.x, cA0);
            cA0 = ffma2(wa.y, ua.y, cA0);
            cA1 = ffma2(wb.x, ua.x, cA1);
            cA1 = ffma2(wb.y, ua.y, cA1);
            cB0 = ffma2(wa.x, ub.x, cB0);
            cB0 = ffma2(wa.y, ub.y, cB0);
            cB1 = ffma2(wb.x, ub.x, cB1);
            cB1 = ffma2(wb.y, ub.y, cB1);
        }
        float2 gA0 = unpk(cA0), gA1 = unpk(cA1);
        float2 gB0 = unpk(cB0), gB1 = unpk(cB1);

        atomicAdd(out + (long)curA * NE + lane,      0.1f * (gA0.x + gA0.y));
        atomicAdd(out + (long)curA * NE + lane + 32, 0.1f * (gA1.x + gA1.y));
        if (curVB) {
            atomicAdd(out + (long)curB * NE + lane,      0.1f * (gB0.x + gB0.y));
            atomicAdd(out + (long)curB * NE + lane + 32, 0.1f * (gB1.x + gB1.y));
        }

        if (!hasNext) break;
    }
}

extern "C" void kernel_launch(void* const* d_in, const int* in_sizes, int n_in,
                              void* d_out, int out_size) {
    const int*           x     = (const int*)d_in[0];
    const float*         table = (const float*)d_in[1];
    const float*         W1    = (const float*)d_in[2];
    const float*         W2    = (const float*)d_in[3];
    const unsigned char* mem   = (const unsigned char*)d_in[4];
    float* out = (float*)d_out;

    const int T = in_sizes[0];

    prep_kernel<<<(ND * NE * NK + 255) / 256, 256>>>(W1, W2);
    build_copy<<<(T + 255) / 256, 256>>>(x, mem, table, out, T);
    domain_mlp<<<ND * BLK_PER_DOM, MLP_WARPS * 32>>>(x, table, out);
}

// round 8
// speedup vs baseline: 1.4375x; 1.2625x over previous
#include <cuda_runtime.h>
#include <cuda_bf16.h>

#define ND   16    // domains
#define NE   64    // embedding dim
#define NK   32    // bottleneck dim
#define CAP  8192  // per-domain token-list capacity (expected ~3277)

// ---- device scratch (allocation-free; zero-initialized at load) ----
__device__ int g_cnt[ND];
__device__ int g_list[ND * CAP];   // position index t
__device__ int g_ltok[ND * CAP];   // token id x[t]

typedef unsigned long long ull;

__device__ __forceinline__ ull ffma2(ull a, ull b, ull c) {
    ull d;
    asm("fma.rn.f32x2 %0, %1, %2, %3;" : "=l"(d) : "l"(a), "l"(b), "l"(c));
    return d;
}
__device__ __forceinline__ float2 unpk(ull v) {
    unsigned lo, hi;
    asm("mov.b64 {%0, %1}, %2;" : "=r"(lo), "=r"(hi) : "l"(v));
    return make_float2(__uint_as_float(lo), __uint_as_float(hi));
}
__device__ __forceinline__ ull pk(float lo, float hi) {
    ull v;
    asm("mov.b64 %0, {%1, %2};" : "=l"(v) : "r"(__float_as_uint(lo)), "r"(__float_as_uint(hi)));
    return v;
}

// ------------------------------------------------------------------
// 0) zero the 16 per-domain counters (trivial)
// ------------------------------------------------------------------
__global__ void zero_cnt() {
    if (threadIdx.x < ND) g_cnt[threadIdx.x] = 0;
}

// ------------------------------------------------------------------
// 1) fused: build per-domain token lists + coalesced base copy
// ------------------------------------------------------------------
__global__ __launch_bounds__(256)
void build_copy(const int* __restrict__ x,
                const unsigned char* __restrict__ membership,
                const float* __restrict__ table,
                float* __restrict__ out,
                int T) {
    __shared__ int scnt[ND];
    __shared__ int sbase[ND];
    __shared__ int stok[256];

    const int t = blockIdx.x * 256 + threadIdx.x;
    if (threadIdx.x < ND) scnt[threadIdx.x] = 0;
    __syncthreads();

    unsigned act = 0;
    int mypos[ND];
    int tok = 0;
    if (t < T) {
        tok = x[t];
        stok[threadIdx.x] = tok;
        const unsigned char* __restrict__ mrow = membership + (long)tok * ND;
        #pragma unroll
        for (int d = 0; d < ND; ++d) {
            if (mrow[d]) {
                act |= (1u << d);
                mypos[d] = atomicAdd(&scnt[d], 1);
            }
        }
    }
    __syncthreads();
    if (threadIdx.x < ND)
        sbase[threadIdx.x] = atomicAdd(&g_cnt[threadIdx.x], scnt[threadIdx.x]);
    __syncthreads();
    if (t < T) {
        #pragma unroll
        for (int d = 0; d < ND; ++d) {
            if (act & (1u << d)) {
                int pos = sbase[d] + mypos[d];
                if (pos < CAP) {
                    g_list[d * CAP + pos] = t;
                    g_ltok[d * CAP + pos] = tok;
                }
            }
        }
    }

    // coalesced base-embedding copy for this block's 256 tokens
    const float4* __restrict__ table4 = reinterpret_cast<const float4*>(table);
    float4* __restrict__ out4 = reinterpret_cast<float4*>(out);
    const long blk_base = (long)blockIdx.x * 256;
    for (int j = threadIdx.x; j < 256 * 16; j += 256) {
        const int tl = j >> 4;
        const int c  = j & 15;
        const long gt = blk_base + tl;
        if (gt < T)
            out4[gt * 16 + c] = __ldg(table4 + (long)stok[tl] * 16 + c);
    }
}

// ------------------------------------------------------------------
// 2) per-domain MLP: self-staged weights (W1 regs packed, W2 smem),
//    packed f32x2 math, 4-token interleave, depth-2 prefetch.
// ------------------------------------------------------------------
#define BLK_PER_DOM 27
#define MLP_WARPS   4
#define W1S 33            // sw1 row stride (conflict-free scalar LDS)
#define W2S 36            // sw2 row stride (16B-aligned rows, conflict-free LDS.128)

__global__ __launch_bounds__(MLP_WARPS * 32, 3)
void domain_mlp(const float* __restrict__ W1,
                const float* __restrict__ W2,
                const float* __restrict__ table,
                float* __restrict__ out) {
    __shared__ float sw1[NE * W1S];            // staged W1[e][k]
    __shared__ float sw2[NE * W2S];            // W2 as [e][k] padded rows
    __shared__ float hs[4][MLP_WARPS][NE];
    __shared__ float us[4][MLP_WARPS][NK];

    const int w    = threadIdx.x >> 5;
    const int lane = threadIdx.x & 31;
    const int d     = blockIdx.x & 15;
    const int chunk = blockIdx.x >> 4;
    const int ws    = BLK_PER_DOM * MLP_WARPS;    // warps per domain (108)

    // ---- stage this domain's weights from NATIVE layout (coalesced) ----
    {
        const float* __restrict__ W1n = W1 + (d << 11);   // [e][k]
        const float* __restrict__ W2n = W2 + (d << 11);   // [k][e]
        for (int i = threadIdx.x; i < NE * NK; i += MLP_WARPS * 32) {
            int e = i >> 5, k = i & 31;
            sw1[e * W1S + k] = W1n[i];
            int k2 = i >> 6, e2 = i & 63;
            sw2[e2 * W2S + k2] = W2n[i];
        }
    }
    __syncthreads();

    int cnt = g_cnt[d];
    if (cnt > CAP) cnt = CAP;
    int i0 = chunk * MLP_WARPS + w;
    if (i0 >= cnt) return;

    // ---- W1 column (lane = k) as 32 packed f32x2 regs ----
    ull w1p[32];
    #pragma unroll
    for (int i = 0; i < 32; ++i)
        w1p[i] = pk(sw1[(2 * i) * W1S + lane], sw1[(2 * i + 1) * W1S + lane]);

    const int* __restrict__ list = g_list + d * CAP;
    const int* __restrict__ ltok = g_ltok + d * CAP;

    const ulonglong2* __restrict__ hp0 = reinterpret_cast<const ulonglong2*>(hs[0][w]);
    const ulonglong2* __restrict__ hp1 = reinterpret_cast<const ulonglong2*>(hs[1][w]);
    const ulonglong2* __restrict__ hp2 = reinterpret_cast<const ulonglong2*>(hs[2][w]);
    const ulonglong2* __restrict__ hp3 = reinterpret_cast<const ulonglong2*>(hs[3][w]);
    const ulonglong2* __restrict__ up0 = reinterpret_cast<const ulonglong2*>(us[0][w]);
    const ulonglong2* __restrict__ up1 = reinterpret_cast<const ulonglong2*>(us[1][w]);
    const ulonglong2* __restrict__ up2 = reinterpret_cast<const ulonglong2*>(us[2][w]);
    const ulonglong2* __restrict__ up3 = reinterpret_cast<const ulonglong2*>(us[3][w]);
    const ulonglong2* __restrict__ w2r0 = reinterpret_cast<const ulonglong2*>(sw2 + lane * W2S);
    const ulonglong2* __restrict__ w2r1 = reinterpret_cast<const ulonglong2*>(sw2 + (lane + 32) * W2S);
    const float2* __restrict__ table2 = reinterpret_cast<const float2*>(table);

    // ---- prefetch first group of 4 ----
    int  i1 = i0 + ws, i2 = i0 + 2 * ws, i3 = i0 + 3 * ws;
    bool v1 = (i1 < cnt), v2 = (i2 < cnt), v3 = (i3 < cnt);
    int t0 = __ldg(list + i0);
    int t1 = v1 ? __ldg(list + i1) : t0;
    int t2 = v2 ? __ldg(list + i2) : t0;
    int t3 = v3 ? __ldg(list + i3) : t0;
    int k0 = __ldg(ltok + i0);
    int k1 = v1 ? __ldg(ltok + i1) : k0;
    int k2_ = v2 ? __ldg(ltok + i2) : k0;
    int k3 = v3 ? __ldg(ltok + i3) : k0;
    float2 h0 = __ldg(table2 + (long)k0 * 32 + lane);
    float2 h1 = __ldg(table2 + (long)k1 * 32 + lane);
    float2 h2 = __ldg(table2 + (long)k2_ * 32 + lane);
    float2 h3 = __ldg(table2 + (long)k3 * 32 + lane);

    while (true) {
        __syncwarp();
        reinterpret_cast<float2*>(hs[0][w])[lane] = h0;
        reinterpret_cast<float2*>(hs[1][w])[lane] = h1;
        reinterpret_cast<float2*>(hs[2][w])[lane] = h2;
        reinterpret_cast<float2*>(hs[3][w])[lane] = h3;
        __syncwarp();

        const int  c0 = t0, c1 = t1, c2 = t2, c3 = t3;
        const bool cv1 = v1, cv2 = v2, cv3 = v3;

        // ---- prefetch next group (overlaps compute) ----
        i0 += 4 * ws; i1 += 4 * ws; i2 += 4 * ws; i3 += 4 * ws;
        const bool hasNext = (i0 < cnt);
        if (hasNext) {
            v1 = (i1 < cnt); v2 = (i2 < cnt); v3 = (i3 < cnt);
            t0 = __ldg(list + i0);
            t1 = v1 ? __ldg(list + i1) : t0;
            t2 = v2 ? __ldg(list + i2) : t0;
            t3 = v3 ? __ldg(list + i3) : t0;
            k0 = __ldg(ltok + i0);
            k1 = v1 ? __ldg(ltok + i1) : k0;
            k2_ = v2 ? __ldg(ltok + i2) : k0;
            k3 = v3 ? __ldg(ltok + i3) : k0;
            h0 = __ldg(table2 + (long)k0 * 32 + lane);
            h1 = __ldg(table2 + (long)k1 * 32 + lane);
            h2 = __ldg(table2 + (long)k2_ * 32 + lane);
            h3 = __ldg(table2 + (long)k3 * 32 + lane);
        }

        // ---- stage 1: u[k] = gelu(h · W1[:,k]); 8 independent chains ----
        ull a0x = 0, a0y = 0, a1x = 0, a1y = 0;
        ull a2x = 0, a2y = 0, a3x = 0, a3y = 0;
        #pragma unroll
        for (int i = 0; i < 16; ++i) {
            ulonglong2 q0 = hp0[i], q1 = hp1[i], q2 = hp2[i], q3 = hp3[i];
            ull wlo = w1p[2 * i], whi = w1p[2 * i + 1];
            a0x = ffma2(wlo, q0.x, a0x);  a0y = ffma2(whi, q0.y, a0y);
            a1x = ffma2(wlo, q1.x, a1x);  a1y = ffma2(whi, q1.y, a1y);
            a2x = ffma2(wlo, q2.x, a2x);  a2y = ffma2(whi, q2.y, a2y);
            a3x = ffma2(wlo, q3.x, a3x);  a3y = ffma2(whi, q3.y, a3y);
        }
        float2 f0x = unpk(a0x), f0y = unpk(a0y);
        float2 f1x = unpk(a1x), f1y = unpk(a1y);
        float2 f2x = unpk(a2x), f2y = unpk(a2y);
        float2 f3x = unpk(a3x), f3y = unpk(a3y);
        const float s0 = (f0x.x + f0x.y) + (f0y.x + f0y.y);
        const float s1 = (f1x.x + f1x.y) + (f1y.x + f1y.y);
        const float s2 = (f2x.x + f2x.y) + (f2y.x + f2y.y);
        const float s3 = (f3x.x + f3x.y) + (f3y.x + f3y.y);
        const float RS2 = 0.70710678118654752f;
        us[0][w][lane] = 0.5f * s0 * (1.f + erff(s0 * RS2));
        us[1][w][lane] = 0.5f * s1 * (1.f + erff(s1 * RS2));
        us[2][w][lane] = 0.5f * s2 * (1.f + erff(s2 * RS2));
        us[3][w][lane] = 0.5f * s3 * (1.f + erff(s3 * RS2));
        __syncwarp();

        // ---- stage 2: corr[e] = u · W2[e][:]; 8 packed chains ----
        ull cA0 = 0, cA1 = 0, cB0 = 0, cB1 = 0;
        ull cC0 = 0, cC1 = 0, cD0 = 0, cD1 = 0;
        #pragma unroll
        for (int i = 0; i < 8; ++i) {
            ulonglong2 wa = w2r0[i];
            ulonglong2 wb = w2r1[i];
            ulonglong2 u0 = up0[i], u1 = up1[i], u2 = up2[i], u3 = up3[i];
            cA0 = ffma2(wa.x, u0.x, cA0); cA0 = ffma2(wa.y, u0.y, cA0);
            cA1 = ffma2(wb.x, u0.x, cA1); cA1 = ffma2(wb.y, u0.y, cA1);
            cB0 = ffma2(wa.x, u1.x, cB0); cB0 = ffma2(wa.y, u1.y, cB0);
            cB1 = ffma2(wb.x, u1.x, cB1); cB1 = ffma2(wb.y, u1.y, cB1);
            cC0 = ffma2(wa.x, u2.x, cC0); cC0 = ffma2(wa.y, u2.y, cC0);
            cC1 = ffma2(wb.x, u2.x, cC1); cC1 = ffma2(wb.y, u2.y, cC1);
            cD0 = ffma2(wa.x, u3.x, cD0); cD0 = ffma2(wa.y, u3.y, cD0);
            cD1 = ffma2(wb.x, u3.x, cD1); cD1 = ffma2(wb.y, u3.y, cD1);
        }
        float2 gA0 = unpk(cA0), gA1 = unpk(cA1);
        float2 gB0 = unpk(cB0), gB1 = unpk(cB1);
        float2 gC0 = unpk(cC0), gC1 = unpk(cC1);
        float2 gD0 = unpk(cD0), gD1 = unpk(cD1);

        atomicAdd(out + (long)c0 * NE + lane,      0.1f * (gA0.x + gA0.y));
        atomicAdd(out + (long)c0 * NE + lane + 32, 0.1f * (gA1.x + gA1.y));
        if (cv1) {
            atomicAdd(out + (long)c1 * NE + lane,      0.1f * (gB0.x + gB0.y));
            atomicAdd(out + (long)c1 * NE + lane + 32, 0.1f * (gB1.x + gB1.y));
        }
        if (cv2) {
            atomicAdd(out + (long)c2 * NE + lane,      0.1f * (gC0.x + gC0.y));
            atomicAdd(out + (long)c2 * NE + lane + 32, 0.1f * (gC1.x + gC1.y));
        }
        if (cv3) {
            atomicAdd(out + (long)c3 * NE + lane,      0.1f * (gD0.x + gD0.y));
            atomicAdd(out + (long)c3 * NE + lane + 32, 0.1f * (gD1.x + gD1.y));
        }

        if (!hasNext) break;
    }
}

extern "C" void kernel_launch(void* const* d_in, const int* in_sizes, int n_in,
                              void* d_out, int out_size) {
    const int*           x     = (const int*)d_in[0];
    const float*         table = (const float*)d_in[1];
    const float*         W1    = (const float*)d_in[2];
    const float*         W2    = (const float*)d_in[3];
    const unsigned char* mem   = (const unsigned char*)d_in[4];
    float* out = (float*)d_out;

    const int T = in_sizes[0];

    zero_cnt<<<1, 32>>>();
    build_copy<<<(T + 255) / 256, 256>>>(x, mem, table, out, T);
    domain_mlp<<<ND * BLK_PER_DOM, MLP_WARPS * 32>>>(W1, W2, table, out);
}